// round 6
// baseline (speedup 1.0000x reference)
#include <cuda_runtime.h>

// Problem shape (fixed by the dataset; inputs arrive as float32)
constexpr int B  = 2;
constexpr int H  = 32;
constexpr int S  = 8192;
constexpr int D  = 128;
constexpr int BH = B * H;          // 64
constexpr int NS = 64;             // split-K chunks
constexpr int C  = S / NS;         // 128 rows per chunk

// Split-K scratch (no cudaMalloc allowed -> device globals; zero-initialized)
__device__ float        g_m[BH * NS];
__device__ float        g_l[BH * NS];
__device__ float        g_o[(size_t)BH * NS * D];
__device__ unsigned int g_cnt[BH];

__device__ __forceinline__ float4 ldcs4(const float* p) {
    return __ldcs((const float4*)p);   // streaming: evict-first, no L2 persist
}

// ---------------------------------------------------------------------------
// Fused flash-decoding kernel.
// grid = (NS, BH), block = 256 (8 warps). Warp w owns rows [16w, 16w+16),
// lane l owns dims [4l, 4l+4). Each CTA streams one 64KB K tile + 64KB V tile,
// writes partials; the LAST CTA to finish a bh combines all 64 chunks.
// ---------------------------------------------------------------------------
__global__ __launch_bounds__(256, 4)
void nd_fused_kernel(const float* __restrict__ q,
                     const float* __restrict__ k,
                     const float* __restrict__ v,
                     float* __restrict__ out)
{
    const int chunk = blockIdx.x;
    const int bh    = blockIdx.y;
    const int tid   = threadIdx.x;
    const int wid   = tid >> 5;
    const int lane  = tid & 31;

    __shared__ float  sc[C];           // scores -> probabilities
    __shared__ float  red[8];          // cross-warp reduce
    __shared__ float4 opart[8][32];    // per-warp partial o vectors
    __shared__ float  s_m;
    __shared__ int    s_last;

    const float4 qf = *(const float4*)(q + (size_t)bh * D + 4 * lane);

    const size_t base = ((size_t)bh * S + (size_t)chunk * C) * D;
    const float* __restrict__ kg = k + base;
    const float* __restrict__ vg = v + base;

    // ---- Scores: s[r] = (q . k_r) * scale ---------------------------------
    #pragma unroll
    for (int i = 0; i < 16; i++) {
        const int r = wid * 16 + i;
        const float4 kf = ldcs4(kg + (size_t)r * D + 4 * lane);
        float d = kf.x * qf.x + kf.y * qf.y + kf.z * qf.z + kf.w * qf.w;
        #pragma unroll
        for (int o = 16; o; o >>= 1) d += __shfl_xor_sync(~0u, d, o);
        if (lane == 0) sc[r] = d * 0.08838834764831845f;  // 1/sqrt(128)
    }
    __syncthreads();

    // ---- Chunk max ----------------------------------------------------------
    const float sval = (tid < C) ? sc[tid] : -1e30f;
    float mv = sval;
    #pragma unroll
    for (int o = 16; o; o >>= 1) mv = fmaxf(mv, __shfl_xor_sync(~0u, mv, o));
    if (lane == 0) red[wid] = mv;
    __syncthreads();
    if (tid == 0) {
        float mm = red[0];
        #pragma unroll
        for (int i = 1; i < 8; i++) mm = fmaxf(mm, red[i]);
        s_m = mm;
    }
    __syncthreads();
    const float m = s_m;

    // ---- p = exp(s - m), l = sum p ------------------------------------------
    const float p = (tid < C) ? __expf(sval - m) : 0.f;
    if (tid < C) sc[tid] = p;
    float sv = p;
    #pragma unroll
    for (int o = 16; o; o >>= 1) sv += __shfl_xor_sync(~0u, sv, o);
    if (lane == 0) red[wid] = sv;
    __syncthreads();                 // also orders sc[] writes before V loop
    if (tid == 0) {
        float ll = 0.f;
        #pragma unroll
        for (int i = 0; i < 8; i++) ll += red[i];
        g_m[bh * NS + chunk] = m;
        g_l[bh * NS + chunk] = ll;
    }

    // ---- o = sum_r p[r] * v_r  (lane owns 4 dims) ----------------------------
    float4 acc = make_float4(0.f, 0.f, 0.f, 0.f);
    #pragma unroll
    for (int i = 0; i < 16; i++) {
        const int r = wid * 16 + i;
        const float pw = sc[r];
        const float4 vf = ldcs4(vg + (size_t)r * D + 4 * lane);
        acc.x += pw * vf.x;  acc.y += pw * vf.y;
        acc.z += pw * vf.z;  acc.w += pw * vf.w;
    }
    opart[wid][lane] = acc;
    __syncthreads();

    if (tid < C) {
        float s = 0.f;
        #pragma unroll
        for (int w = 0; w < 8; w++)
            s += ((const float*)&opart[w][0])[tid];
        g_o[((size_t)bh * NS + chunk) * D + tid] = s;
    }

    // ---- Arrival: last CTA of this bh does the combine -----------------------
    __threadfence();                 // make g_m/g_l/g_o visible device-wide
    __syncthreads();                 // all warps' stores precede the arrival
    if (tid == 0) {
        const unsigned int old = atomicAdd(&g_cnt[bh], 1u);
        s_last = (old == NS - 1);
        if (s_last) g_cnt[bh] = 0;   // safe: all NS increments already done;
                                     // leaves counter ready for graph replay
    }
    __syncthreads();
    if (!s_last) return;

    // ================= Combine (one CTA per bh, 256 threads) ================
    // Reuse shared: sc[0..63] = m_c, red-free. alpha in sc2, partial sums in opart.
    __shared__ float al[NS];
    __shared__ float s_L;

    if (tid < NS) sc[tid] = g_m[bh * NS + tid];          // m values
    if (tid >= 64 && tid < 64 + NS) al[tid - 64] = g_l[bh * NS + (tid - 64)]; // l values
    __syncthreads();

    if (tid < 32) {
        float mm = fmaxf(sc[tid], sc[tid + 32]);
        #pragma unroll
        for (int o = 16; o; o >>= 1) mm = fmaxf(mm, __shfl_xor_sync(~0u, mm, o));
        const float M = mm;          // uniform after full butterfly
        const float a0 = __expf(sc[tid]      - M);
        const float a1 = __expf(sc[tid + 32] - M);
        float lv = al[tid] * a0 + al[tid + 32] * a1;
        #pragma unroll
        for (int o = 16; o; o >>= 1) lv += __shfl_xor_sync(~0u, lv, o);
        al[tid]      = a0;           // overwrite l with alpha
        al[tid + 32] = a1;
        if (tid == 0) s_L = lv;
    }
    __syncthreads();

    // Thread (h, d): h = tid>>7 in {0,1}, d = tid&127. Sum 32 chunks each.
    const int d = tid & 127;
    const int h = tid >> 7;
    float accv = 0.f;
    const float* __restrict__ ob = g_o + (size_t)bh * NS * D + d;
    #pragma unroll 8
    for (int j = 0; j < 32; j++) {
        const int c = h * 32 + j;
        accv += ob[(size_t)c * D] * al[c];
    }
    ((float*)opart)[h * 128 + d] = accv;
    __syncthreads();

    if (tid < 128) {
        const float s = ((float*)opart)[tid] + ((float*)opart)[128 + tid];
        out[(size_t)bh * D + tid] = s / s_L;
    }
}

// ---------------------------------------------------------------------------
extern "C" void kernel_launch(void* const* d_in, const int* in_sizes, int n_in,
                              void* d_out, int out_size)
{
    const float* q = (const float*)d_in[0];
    const float* k = (const float*)d_in[1];
    const float* v = (const float*)d_in[2];
    float* out = (float*)d_out;

    dim3 grid(NS, BH);
    nd_fused_kernel<<<grid, 256>>>(q, k, v, out);
}

// round 8
// speedup vs baseline: 1.0086x; 1.0086x over previous
#include <cuda_runtime.h>

// Problem shape (fixed by the dataset; inputs arrive as float32)
constexpr int B  = 2;
constexpr int H  = 32;
constexpr int S  = 8192;
constexpr int D  = 128;
constexpr int BH = B * H;          // 64
constexpr int NS = 64;             // split-K chunks
constexpr int C  = S / NS;         // 128 rows per chunk

// Split-K scratch (no cudaMalloc allowed -> device globals)
__device__ float g_m[BH * NS];
__device__ float g_l[BH * NS];
__device__ float g_o[(size_t)BH * NS * D];

__device__ __forceinline__ float4 ldcs4(const float* p) {
    return __ldcs((const float4*)p);   // streaming K/V: evict-first in L2
}
// Scratch stores: L2 evict-last policy via cache_hint (scalar-width legal form)
// so the combine kernel hits L2 instead of DRAM.
__device__ __forceinline__ void stel(float* p, float v) {
    asm volatile(
        "{\n\t"
        ".reg .b64 pol;\n\t"
        "createpolicy.fractional.L2::evict_last.b64 pol, 1.0;\n\t"
        "st.global.L2::cache_hint.f32 [%0], %1, pol;\n\t"
        "}" :: "l"(p), "f"(v) : "memory");
}

// ---------------------------------------------------------------------------
// Kernel 1: per-chunk partial attention.  (math unchanged — at HBM roofline)
// grid = (NS, BH), block = 256 (8 warps). Warp w owns rows [16w, 16w+16),
// lane l owns dims [4l, 4l+4). Each CTA streams one 64KB K tile + 64KB V tile.
// ---------------------------------------------------------------------------
__global__ __launch_bounds__(256, 4)
void nd_partial_kernel(const float* __restrict__ q,
                       const float* __restrict__ k,
                       const float* __restrict__ v)
{
    const int chunk = blockIdx.x;
    const int bh    = blockIdx.y;
    const int tid   = threadIdx.x;
    const int wid   = tid >> 5;
    const int lane  = tid & 31;

    __shared__ float  sc[C];           // scores -> probabilities
    __shared__ float  red[8];          // cross-warp reduce
    __shared__ float4 opart[8][32];    // per-warp partial o vectors
    __shared__ float  s_m;

    const float4 qf = *(const float4*)(q + (size_t)bh * D + 4 * lane);

    const size_t base = ((size_t)bh * S + (size_t)chunk * C) * D;
    const float* __restrict__ kg = k + base;
    const float* __restrict__ vg = v + base;

    // ---- Scores: s[r] = (q . k_r) * scale ---------------------------------
    #pragma unroll
    for (int i = 0; i < 16; i++) {
        const int r = wid * 16 + i;
        const float4 kf = ldcs4(kg + (size_t)r * D + 4 * lane);
        float d = kf.x * qf.x + kf.y * qf.y + kf.z * qf.z + kf.w * qf.w;
        #pragma unroll
        for (int o = 16; o; o >>= 1) d += __shfl_xor_sync(~0u, d, o);
        if (lane == 0) sc[r] = d * 0.08838834764831845f;  // 1/sqrt(128)
    }
    __syncthreads();

    // ---- Chunk max ----------------------------------------------------------
    const float sval = (tid < C) ? sc[tid] : -1e30f;
    float mv = sval;
    #pragma unroll
    for (int o = 16; o; o >>= 1) mv = fmaxf(mv, __shfl_xor_sync(~0u, mv, o));
    if (lane == 0) red[wid] = mv;
    __syncthreads();
    if (tid == 0) {
        float mm = red[0];
        #pragma unroll
        for (int i = 1; i < 8; i++) mm = fmaxf(mm, red[i]);
        s_m = mm;
    }
    __syncthreads();
    const float m = s_m;

    // ---- p = exp(s - m), l = sum p ------------------------------------------
    const float p = (tid < C) ? __expf(sval - m) : 0.f;
    if (tid < C) sc[tid] = p;
    float sv = p;
    #pragma unroll
    for (int o = 16; o; o >>= 1) sv += __shfl_xor_sync(~0u, sv, o);
    if (lane == 0) red[wid] = sv;
    __syncthreads();                 // also orders sc[] writes before V loop
    if (tid == 0) {
        float ll = 0.f;
        #pragma unroll
        for (int i = 0; i < 8; i++) ll += red[i];
        stel(&g_m[bh * NS + chunk], m);
        stel(&g_l[bh * NS + chunk], ll);
    }

    // ---- o = sum_r p[r] * v_r  (lane owns 4 dims) ----------------------------
    float4 acc = make_float4(0.f, 0.f, 0.f, 0.f);
    #pragma unroll
    for (int i = 0; i < 16; i++) {
        const int r = wid * 16 + i;
        const float pw = sc[r];
        const float4 vf = ldcs4(vg + (size_t)r * D + 4 * lane);
        acc.x += pw * vf.x;  acc.y += pw * vf.y;
        acc.z += pw * vf.z;  acc.w += pw * vf.w;
    }
    opart[wid][lane] = acc;
    __syncthreads();

    if (tid < C) {
        float s = 0.f;
        #pragma unroll
        for (int w = 0; w < 8; w++)
            s += ((const float*)&opart[w][0])[tid];
        stel(&g_o[((size_t)bh * NS + chunk) * D + tid], s);
    }
}

// ---------------------------------------------------------------------------
// Kernel 2: cross-chunk online-softmax combine.
// grid = (BH, 4), block = 256. CTA (bh, g) produces dims [32g, 32g+32).
// Thread (cg, d32): cg = tid>>5 sums chunks [8cg, 8cg+8) for dim g*32+d32.
// M and L are computed redundantly per CTA by warp 0 (cheap).
// ---------------------------------------------------------------------------
__global__ __launch_bounds__(256)
void nd_combine_kernel(float* __restrict__ out)
{
    const int bh  = blockIdx.x;
    const int g   = blockIdx.y;
    const int tid = threadIdx.x;
    const int d32 = tid & 31;
    const int cg  = tid >> 5;      // 0..7

    __shared__ float sm[NS];       // m values
    __shared__ float al[NS];       // l values -> alpha
    __shared__ float s_L;
    __shared__ float part[8][32];

    if (tid < NS)               sm[tid]       = g_m[bh * NS + tid];
    if (tid >= 64 && tid < 128) al[tid - 64]  = g_l[bh * NS + (tid - 64)];
    __syncthreads();

    if (tid < 32) {
        float mm = fmaxf(sm[tid], sm[tid + 32]);
        #pragma unroll
        for (int o = 16; o; o >>= 1) mm = fmaxf(mm, __shfl_xor_sync(~0u, mm, o));
        const float M  = mm;       // uniform after full butterfly
        const float a0 = __expf(sm[tid]      - M);
        const float a1 = __expf(sm[tid + 32] - M);
        float lv = al[tid] * a0 + al[tid + 32] * a1;
        #pragma unroll
        for (int o = 16; o; o >>= 1) lv += __shfl_xor_sync(~0u, lv, o);
        al[tid]      = a0;         // overwrite l with alpha
        al[tid + 32] = a1;
        if (tid == 0) s_L = lv;
    }
    __syncthreads();

    const int d = g * 32 + d32;
    float acc = 0.f;
    const float* __restrict__ ob = g_o + (size_t)bh * NS * D + d;
    #pragma unroll
    for (int j = 0; j < 8; j++) {
        const int c = cg * 8 + j;
        acc += ob[(size_t)c * D] * al[c];
    }
    part[cg][d32] = acc;
    __syncthreads();

    if (cg == 0) {
        float s = 0.f;
        #pragma unroll
        for (int j = 0; j < 8; j++) s += part[j][d32];
        out[(size_t)bh * D + d] = s / s_L;
    }
}

// ---------------------------------------------------------------------------
extern "C" void kernel_launch(void* const* d_in, const int* in_sizes, int n_in,
                              void* d_out, int out_size)
{
    const float* q = (const float*)d_in[0];
    const float* k = (const float*)d_in[1];
    const float* v = (const float*)d_in[2];
    float* out = (float*)d_out;

    dim3 grid1(NS, BH);
    nd_partial_kernel<<<grid1, 256>>>(q, k, v);
    dim3 grid2(BH, 4);
    nd_combine_kernel<<<grid2, 256>>>(out);
}

// round 9
// speedup vs baseline: 1.0336x; 1.0248x over previous
#include <cuda_runtime.h>
#include <cuda_fp16.h>

// Problem shape (fixed by the dataset; inputs arrive as float32)
constexpr int B  = 2;
constexpr int H  = 32;
constexpr int S  = 8192;
constexpr int D  = 128;
constexpr int BH = B * H;          // 64
constexpr int NS = 64;             // split-K chunks
constexpr int C  = S / NS;         // 128 rows per chunk

// Split-K scratch (no cudaMalloc allowed -> device globals)
// o partials in fp16: halves scratch write + combine read traffic.
__device__ float  g_m[BH * NS];
__device__ float  g_l[BH * NS];
__device__ __half g_oh[(size_t)BH * NS * D];

__device__ __forceinline__ float4 ldcs4(const float* p) {
    return __ldcs((const float4*)p);   // streaming K/V: evict-first in L2
}

// ---------------------------------------------------------------------------
// Kernel 1: per-chunk partial attention.  (round-5 form — at HBM roofline)
// grid = (NS, BH), block = 256 (8 warps). Warp w owns rows [16w, 16w+16),
// lane l owns dims [4l, 4l+4). Each CTA streams one 64KB K tile + 64KB V tile.
// ---------------------------------------------------------------------------
__global__ __launch_bounds__(256, 4)
void nd_partial_kernel(const float* __restrict__ q,
                       const float* __restrict__ k,
                       const float* __restrict__ v)
{
    const int chunk = blockIdx.x;
    const int bh    = blockIdx.y;
    const int tid   = threadIdx.x;
    const int wid   = tid >> 5;
    const int lane  = tid & 31;

    __shared__ float  sc[C];           // scores -> probabilities
    __shared__ float  red[8];          // cross-warp reduce
    __shared__ float4 opart[8][32];    // per-warp partial o vectors
    __shared__ float  s_m;

    const float4 qf = *(const float4*)(q + (size_t)bh * D + 4 * lane);

    const size_t base = ((size_t)bh * S + (size_t)chunk * C) * D;
    const float* __restrict__ kg = k + base;
    const float* __restrict__ vg = v + base;

    // ---- Scores: s[r] = (q . k_r) * scale ---------------------------------
    #pragma unroll
    for (int i = 0; i < 16; i++) {
        const int r = wid * 16 + i;
        const float4 kf = ldcs4(kg + (size_t)r * D + 4 * lane);
        float d = kf.x * qf.x + kf.y * qf.y + kf.z * qf.z + kf.w * qf.w;
        #pragma unroll
        for (int o = 16; o; o >>= 1) d += __shfl_xor_sync(~0u, d, o);
        if (lane == 0) sc[r] = d * 0.08838834764831845f;  // 1/sqrt(128)
    }
    __syncthreads();

    // ---- Chunk max ----------------------------------------------------------
    const float sval = (tid < C) ? sc[tid] : -1e30f;
    float mv = sval;
    #pragma unroll
    for (int o = 16; o; o >>= 1) mv = fmaxf(mv, __shfl_xor_sync(~0u, mv, o));
    if (lane == 0) red[wid] = mv;
    __syncthreads();
    if (tid == 0) {
        float mm = red[0];
        #pragma unroll
        for (int i = 1; i < 8; i++) mm = fmaxf(mm, red[i]);
        s_m = mm;
    }
    __syncthreads();
    const float m = s_m;

    // ---- p = exp(s - m), l = sum p ------------------------------------------
    const float p = (tid < C) ? __expf(sval - m) : 0.f;
    if (tid < C) sc[tid] = p;
    float sv = p;
    #pragma unroll
    for (int o = 16; o; o >>= 1) sv += __shfl_xor_sync(~0u, sv, o);
    if (lane == 0) red[wid] = sv;
    __syncthreads();                 // also orders sc[] writes before V loop
    if (tid == 0) {
        float ll = 0.f;
        #pragma unroll
        for (int i = 0; i < 8; i++) ll += red[i];
        g_m[bh * NS + chunk] = m;
        g_l[bh * NS + chunk] = ll;
    }

    // ---- o = sum_r p[r] * v_r  (lane owns 4 dims) ----------------------------
    float4 acc = make_float4(0.f, 0.f, 0.f, 0.f);
    #pragma unroll
    for (int i = 0; i < 16; i++) {
        const int r = wid * 16 + i;
        const float pw = sc[r];
        const float4 vf = ldcs4(vg + (size_t)r * D + 4 * lane);
        acc.x += pw * vf.x;  acc.y += pw * vf.y;
        acc.z += pw * vf.z;  acc.w += pw * vf.w;
    }
    opart[wid][lane] = acc;
    __syncthreads();

    if (tid < C) {
        float s = 0.f;
        #pragma unroll
        for (int w = 0; w < 8; w++)
            s += ((const float*)&opart[w][0])[tid];
        g_oh[((size_t)bh * NS + chunk) * D + tid] = __float2half(s);
    }
}

// ---------------------------------------------------------------------------
// Kernel 2: cross-chunk online-softmax combine (fp16 partial reads).
// grid = (BH, 4), block = 256. CTA (bh, g) produces dims [32g, 32g+32).
// Thread (cg, d32): cg = tid>>5 sums chunks [8cg, 8cg+8) for dim g*32+d32.
// ---------------------------------------------------------------------------
__global__ __launch_bounds__(256)
void nd_combine_kernel(float* __restrict__ out)
{
    const int bh  = blockIdx.x;
    const int g   = blockIdx.y;
    const int tid = threadIdx.x;
    const int d32 = tid & 31;
    const int cg  = tid >> 5;      // 0..7

    __shared__ float sm[NS];       // m values
    __shared__ float al[NS];       // l values -> alpha
    __shared__ float s_L;
    __shared__ float part[8][32];

    if (tid < NS)               sm[tid]      = g_m[bh * NS + tid];
    if (tid >= 64 && tid < 128) al[tid - 64] = g_l[bh * NS + (tid - 64)];
    __syncthreads();

    if (tid < 32) {
        float mm = fmaxf(sm[tid], sm[tid + 32]);
        #pragma unroll
        for (int o = 16; o; o >>= 1) mm = fmaxf(mm, __shfl_xor_sync(~0u, mm, o));
        const float M  = mm;       // uniform after full butterfly
        const float a0 = __expf(sm[tid]      - M);
        const float a1 = __expf(sm[tid + 32] - M);
        float lv = al[tid] * a0 + al[tid + 32] * a1;
        #pragma unroll
        for (int o = 16; o; o >>= 1) lv += __shfl_xor_sync(~0u, lv, o);
        al[tid]      = a0;         // overwrite l with alpha
        al[tid + 32] = a1;
        if (tid == 0) s_L = lv;
    }
    __syncthreads();

    const int d = g * 32 + d32;
    float acc = 0.f;
    const __half* __restrict__ ob = g_oh + (size_t)bh * NS * D + d;
    #pragma unroll
    for (int j = 0; j < 8; j++) {
        const int c = cg * 8 + j;
        acc += __half2float(ob[(size_t)c * D]) * al[c];
    }
    part[cg][d32] = acc;
    __syncthreads();

    if (cg == 0) {
        float s = 0.f;
        #pragma unroll
        for (int j = 0; j < 8; j++) s += part[j][d32];
        out[(size_t)bh * D + d] = s / s_L;
    }
}

// ---------------------------------------------------------------------------
extern "C" void kernel_launch(void* const* d_in, const int* in_sizes, int n_in,
                              void* d_out, int out_size)
{
    const float* q = (const float*)d_in[0];
    const float* k = (const float*)d_in[1];
    const float* v = (const float*)d_in[2];
    float* out = (float*)d_out;

    dim3 grid1(NS, BH);
    nd_partial_kernel<<<grid1, 256>>>(q, k, v);
    dim3 grid2(BH, 4);
    nd_combine_kernel<<<grid2, 256>>>(out);
}